// round 1
// baseline (speedup 1.0000x reference)
#include <cuda_runtime.h>
#include <math.h>

#define B_  64
#define C_  1000
#define F_  2048
#define KS  8
#define CP  1024   // padded C stride

// ---------------- scratch (static __device__, no allocations) ----------------
__device__ float g_p_dot[KS][B_ * CP];    // partials: x @ centroids^T
__device__ float g_p_hall[KS][B_ * CP];   // partials: x @ W_hall^T
__device__ float g_p_sel[KS][B_ * F_];    // partials: x @ W_sel^T
__device__ float g_p_mem[KS][B_ * F_];    // partials: vm @ centroids
__device__ float g_p_cos[KS][B_ * CP];    // partials: feat @ W_cos^T
__device__ float g_hall[B_ * CP];
__device__ float g_vm[B_ * CP];
__device__ float g_feat[B_ * F_];
__device__ float g_cn2[CP];
__device__ float g_wn[CP];
__device__ float g_xn2[B_];
__device__ float g_reach[B_];
__device__ float g_scale[B_];

// ---------------- row-wise squared norms / norms ----------------
__global__ __launch_bounds__(256) void norms_kernel(const float* __restrict__ centroids,
                                                    const float* __restrict__ W_cos,
                                                    const float* __restrict__ x) {
    int bid = blockIdx.x;
    const float* src;
    int mode, idx;
    if (bid < C_)            { src = centroids + (size_t)bid * F_;        mode = 0; idx = bid; }
    else if (bid < 2 * C_)   { src = W_cos + (size_t)(bid - C_) * F_;     mode = 1; idx = bid - C_; }
    else                     { src = x + (size_t)(bid - 2 * C_) * F_;     mode = 2; idx = bid - 2 * C_; }
    __shared__ float red[256];
    float s = 0.f;
    for (int i = threadIdx.x; i < F_; i += 256) { float v = src[i]; s += v * v; }
    red[threadIdx.x] = s; __syncthreads();
    for (int o = 128; o > 0; o >>= 1) {
        if (threadIdx.x < o) red[threadIdx.x] += red[threadIdx.x + o];
        __syncthreads();
    }
    if (threadIdx.x == 0) {
        if (mode == 0)      g_cn2[idx] = red[0];
        else if (mode == 1) g_wn[idx]  = sqrtf(red[0]);
        else                g_xn2[idx] = red[0];
    }
}

// ---------------- GEMM NT: P[ks][m][n] = sum_k A[m,k]*Bm[n,k] over k-chunk ----------------
// M is fixed 64. 256 threads, 64x64 tile, BK=16, 4x4 micro-tile.
__global__ __launch_bounds__(256) void gemm_nt(const float* __restrict__ A, int lda,
                                               const float* __restrict__ Bm, int ldb,
                                               float* __restrict__ P, int ldp,
                                               int N, int K, int kchunk) {
    __shared__ float As[16][68];
    __shared__ float Bs[16][68];
    const int n0   = blockIdx.x * 64;
    const int ks   = blockIdx.y;
    const int k0   = ks * kchunk;
    const int kend = min(K, k0 + kchunk);
    const int tid  = threadIdx.x;
    const int ty   = tid >> 4, tx = tid & 15;
    const int lrow = tid >> 2;
    const int lkq  = (tid & 3) * 4;
    const int brow = n0 + lrow;

    float acc[4][4];
#pragma unroll
    for (int i = 0; i < 4; i++)
#pragma unroll
        for (int j = 0; j < 4; j++) acc[i][j] = 0.f;

    for (int kb = k0; kb < kend; kb += 16) {
        if (kb + 16 <= kend) {
            float4 av = *(const float4*)&A[(size_t)lrow * lda + kb + lkq];
            As[lkq + 0][lrow] = av.x; As[lkq + 1][lrow] = av.y;
            As[lkq + 2][lrow] = av.z; As[lkq + 3][lrow] = av.w;
            float4 bv = make_float4(0.f, 0.f, 0.f, 0.f);
            if (brow < N) bv = *(const float4*)&Bm[(size_t)brow * ldb + kb + lkq];
            Bs[lkq + 0][lrow] = bv.x; Bs[lkq + 1][lrow] = bv.y;
            Bs[lkq + 2][lrow] = bv.z; Bs[lkq + 3][lrow] = bv.w;
        } else {
#pragma unroll
            for (int i = 0; i < 4; i++) {
                int k = kb + lkq + i;
                As[lkq + i][lrow] = (k < kend) ? A[(size_t)lrow * lda + k] : 0.f;
                Bs[lkq + i][lrow] = (k < kend && brow < N) ? Bm[(size_t)brow * ldb + k] : 0.f;
            }
        }
        __syncthreads();
#pragma unroll
        for (int kk = 0; kk < 16; kk++) {
            float4 a = *(const float4*)&As[kk][ty * 4];
            float4 b = *(const float4*)&Bs[kk][tx * 4];
            acc[0][0] += a.x * b.x; acc[0][1] += a.x * b.y; acc[0][2] += a.x * b.z; acc[0][3] += a.x * b.w;
            acc[1][0] += a.y * b.x; acc[1][1] += a.y * b.y; acc[1][2] += a.y * b.z; acc[1][3] += a.y * b.w;
            acc[2][0] += a.z * b.x; acc[2][1] += a.z * b.y; acc[2][2] += a.z * b.z; acc[2][3] += a.z * b.w;
            acc[3][0] += a.w * b.x; acc[3][1] += a.w * b.y; acc[3][2] += a.w * b.z; acc[3][3] += a.w * b.w;
        }
        __syncthreads();
    }
    float* Pp = P + (size_t)ks * 64 * ldp;
#pragma unroll
    for (int i = 0; i < 4; i++) {
        int m = ty * 4 + i;
#pragma unroll
        for (int j = 0; j < 4; j++) {
            int n = n0 + tx * 4 + j;
            if (n < N) Pp[(size_t)m * ldp + n] = acc[i][j];
        }
    }
}

// ---------------- GEMM NN: P[ks][m][n] = sum_k A[m,k]*Bm[k,n] over k-chunk ----------------
__global__ __launch_bounds__(256) void gemm_nn(const float* __restrict__ A, int lda,
                                               const float* __restrict__ Bm, int ldb,
                                               float* __restrict__ P, int ldp,
                                               int N, int K, int kchunk) {
    __shared__ float As[16][68];
    __shared__ float Bs[16][68];
    const int n0   = blockIdx.x * 64;
    const int ks   = blockIdx.y;
    const int k0   = ks * kchunk;
    const int kend = min(K, k0 + kchunk);
    const int tid  = threadIdx.x;
    const int ty   = tid >> 4, tx = tid & 15;
    const int lrow = tid >> 2;
    const int lkq  = (tid & 3) * 4;
    const int bkk  = tid >> 4;
    const int bnq  = (tid & 15) * 4;

    float acc[4][4];
#pragma unroll
    for (int i = 0; i < 4; i++)
#pragma unroll
        for (int j = 0; j < 4; j++) acc[i][j] = 0.f;

    for (int kb = k0; kb < kend; kb += 16) {
        if (kb + 16 <= kend) {
            float4 av = *(const float4*)&A[(size_t)lrow * lda + kb + lkq];
            As[lkq + 0][lrow] = av.x; As[lkq + 1][lrow] = av.y;
            As[lkq + 2][lrow] = av.z; As[lkq + 3][lrow] = av.w;
            float4 bv = make_float4(0.f, 0.f, 0.f, 0.f);
            if (n0 + bnq + 3 < N) bv = *(const float4*)&Bm[(size_t)(kb + bkk) * ldb + n0 + bnq];
            *(float4*)&Bs[bkk][bnq] = bv;
        } else {
#pragma unroll
            for (int i = 0; i < 4; i++) {
                int k = kb + lkq + i;
                As[lkq + i][lrow] = (k < kend) ? A[(size_t)lrow * lda + k] : 0.f;
            }
            int k = kb + bkk;
#pragma unroll
            for (int i = 0; i < 4; i++) {
                int n = n0 + bnq + i;
                Bs[bkk][bnq + i] = (k < kend && n < N) ? Bm[(size_t)k * ldb + n] : 0.f;
            }
        }
        __syncthreads();
#pragma unroll
        for (int kk = 0; kk < 16; kk++) {
            float4 a = *(const float4*)&As[kk][ty * 4];
            float4 b = *(const float4*)&Bs[kk][tx * 4];
            acc[0][0] += a.x * b.x; acc[0][1] += a.x * b.y; acc[0][2] += a.x * b.z; acc[0][3] += a.x * b.w;
            acc[1][0] += a.y * b.x; acc[1][1] += a.y * b.y; acc[1][2] += a.y * b.z; acc[1][3] += a.y * b.w;
            acc[2][0] += a.z * b.x; acc[2][1] += a.z * b.y; acc[2][2] += a.z * b.z; acc[2][3] += a.z * b.w;
            acc[3][0] += a.w * b.x; acc[3][1] += a.w * b.y; acc[3][2] += a.w * b.z; acc[3][3] += a.w * b.w;
        }
        __syncthreads();
    }
    float* Pp = P + (size_t)ks * 64 * ldp;
#pragma unroll
    for (int i = 0; i < 4; i++) {
        int m = ty * 4 + i;
#pragma unroll
        for (int j = 0; j < 4; j++) {
            int n = n0 + tx * 4 + j;
            if (n < N) Pp[(size_t)m * ldp + n] = acc[i][j];
        }
    }
}

// ---------------- per-row: reduce partials, min-dist, softmax, reachability ----------------
__global__ __launch_bounds__(256) void row_softmax_kernel(const float* __restrict__ b_hall) {
    const int b = blockIdx.x;
    const int tid = threadIdx.x;
    __shared__ float r0[256], r1[256];
    float mind2 = 1e30f, maxh = -1e30f;
    const float xn2 = g_xn2[b];
    for (int c = tid; c < C_; c += 256) {
        float dot = 0.f, hv = 0.f;
#pragma unroll
        for (int s = 0; s < KS; s++) {
            dot += g_p_dot[s][b * CP + c];
            hv  += g_p_hall[s][b * CP + c];
        }
        hv += b_hall[c];
        g_hall[b * CP + c] = hv;
        float d2 = xn2 + g_cn2[c] - 2.f * dot;
        mind2 = fminf(mind2, d2);
        maxh  = fmaxf(maxh, hv);
    }
    r0[tid] = mind2; r1[tid] = maxh; __syncthreads();
    for (int o = 128; o > 0; o >>= 1) {
        if (tid < o) { r0[tid] = fminf(r0[tid], r0[tid + o]); r1[tid] = fmaxf(r1[tid], r1[tid + o]); }
        __syncthreads();
    }
    const float md2 = r0[0];
    const float mh  = r1[0];
    __syncthreads();
    float se = 0.f;
    for (int c = tid; c < C_; c += 256) se += __expf(g_hall[b * CP + c] - mh);
    r0[tid] = se; __syncthreads();
    for (int o = 128; o > 0; o >>= 1) {
        if (tid < o) r0[tid] += r0[tid + o];
        __syncthreads();
    }
    const float inv = 1.f / r0[0];
    for (int c = tid; c < C_; c += 256)
        g_vm[b * CP + c] = __expf(g_hall[b * CP + c] - mh) * inv;
    if (tid == 0) g_reach[b] = 10.f / sqrtf(fmaxf(md2, 1e-30f));
}

// ---------------- per-row: feat = reach*(x + tanh(sel)*mem), row norm, outputs ----------------
__global__ __launch_bounds__(256) void combine_kernel(const float* __restrict__ x,
                                                      const float* __restrict__ b_sel,
                                                      float* __restrict__ out, int writeFeat) {
    const int b = blockIdx.x;
    const int tid = threadIdx.x;
    __shared__ float red[256];
    const float reach = g_reach[b];
    float n2 = 0.f;
    for (int f = tid; f < F_; f += 256) {
        float mem = 0.f, sz = 0.f;
#pragma unroll
        for (int s = 0; s < KS; s++) {
            mem += g_p_mem[s][b * F_ + f];
            sz  += g_p_sel[s][b * F_ + f];
        }
        float sel  = tanhf(sz + b_sel[f]);
        float xv   = x[(size_t)b * F_ + f];
        float inf  = sel * mem;
        float feat = reach * (xv + inf);
        g_feat[b * F_ + f] = feat;
        n2 += feat * feat;
        if (writeFeat) {
            out[64000 + b * F_ + f]  = xv;   // direct_feature
            out[195072 + b * F_ + f] = inf;  // infused_feature
        }
    }
    red[tid] = n2; __syncthreads();
    for (int o = 128; o > 0; o >>= 1) {
        if (tid < o) red[tid] += red[tid + o];
        __syncthreads();
    }
    // logits scale: 16 / (1 + ||feat||)  (ex = feat/(1+||feat||), SCALE_COS=16 folded)
    if (tid == 0) g_scale[b] = 16.f / (1.f + sqrtf(red[0]));
}

// ---------------- final logits ----------------
__global__ __launch_bounds__(256) void logits_kernel(float* __restrict__ out) {
    int i = blockIdx.x * 256 + threadIdx.x;
    if (i >= B_ * C_) return;
    int b = i / C_, c = i % C_;
    float s = 0.f;
#pragma unroll
    for (int ss = 0; ss < KS; ss++) s += g_p_cos[ss][b * CP + c];
    out[i] = s * g_scale[b] / g_wn[c];
}

// ---------------- launch ----------------
extern "C" void kernel_launch(void* const* d_in, const int* in_sizes, int n_in,
                              void* d_out, int out_size) {
    const float* x         = (const float*)d_in[0];
    const float* centroids = (const float*)d_in[1];
    const float* W_hall    = (const float*)d_in[2];
    const float* b_hall    = (const float*)d_in[3];
    const float* W_sel     = (const float*)d_in[4];
    const float* b_sel     = (const float*)d_in[5];
    const float* W_cos     = (const float*)d_in[6];
    float* out = (float*)d_out;

    float *p_dot, *p_hall, *p_sel, *p_mem, *p_cos, *vm, *feat;
    cudaGetSymbolAddress((void**)&p_dot,  g_p_dot);
    cudaGetSymbolAddress((void**)&p_hall, g_p_hall);
    cudaGetSymbolAddress((void**)&p_sel,  g_p_sel);
    cudaGetSymbolAddress((void**)&p_mem,  g_p_mem);
    cudaGetSymbolAddress((void**)&p_cos,  g_p_cos);
    cudaGetSymbolAddress((void**)&vm,     g_vm);
    cudaGetSymbolAddress((void**)&feat,   g_feat);

    // 1. norms
    norms_kernel<<<2 * C_ + B_, 256>>>(centroids, W_cos, x);

    // 2. three x-side GEMMs (split-K partials)
    gemm_nt<<<dim3(16, KS), 256>>>(x, F_, centroids, F_, p_dot,  CP, C_, F_, 256);
    gemm_nt<<<dim3(16, KS), 256>>>(x, F_, W_hall,    F_, p_hall, CP, C_, F_, 256);
    gemm_nt<<<dim3(32, KS), 256>>>(x, F_, W_sel,     F_, p_sel,  F_, F_, F_, 256);

    // 3. softmax + min-dist + reachability
    row_softmax_kernel<<<B_, 256>>>(b_hall);

    // 4. memory_feature = vm @ centroids  (NN, K = C)
    gemm_nn<<<dim3(32, KS), 256>>>(vm, CP, centroids, F_, p_mem, F_, F_, C_, 128);

    // 5. feat + direct/infused outputs + row norms
    int writeFeat = (out_size >= 326144) ? 1 : 0;
    combine_kernel<<<B_, 256>>>(x, b_sel, out, writeFeat);

    // 6. cos logits GEMM (feat @ W_cos^T)
    gemm_nt<<<dim3(16, KS), 256>>>(feat, F_, W_cos, F_, p_cos, CP, C_, F_, 256);

    // 7. final scaled logits
    logits_kernel<<<250, 256>>>(out);
}